// round 17
// baseline (speedup 1.0000x reference)
#include <cuda_runtime.h>

#define BB 16
#define SS 4096
#define HH 768
#define BPB 32                  // blocks per batch
#define RPB 128                 // rows per block (2 produce rounds x 64)
#define RR  64                  // rows per round (8 producer warps x 8)
#define NPROD 2                 // produce rounds per block
#define NEGV (-1e30f)

// ---------------- scratch (static device globals; no allocation) ----------------
__device__ float g_part[BB * BPB * 9];    // per-block 3x3 semiring partial products
__device__ float g_nump[BB * BPB];        // numerator partials
__device__ int   g_mskp[BB * BPB];        // mask partials
__device__ float g_em0[BB * 3];           // emissions row 0 per batch
__device__ float g_llh[BB];               // per-batch llh
__device__ unsigned int g_cnt[BB];        // per-batch arrival counters (monotonic, mod 32)
__device__ unsigned int g_bcnt;           // finalize counter (monotonic, mod 16)

__device__ __forceinline__ float lse3(float a, float b, float c) {
    float m = fmaxf(a, fmaxf(b, c));
    return m + __logf(__expf(a - m) + __expf(b - m) + __expf(c - m));
}

// ---------------- single warp-specialized kernel ----------------------------------
// grid = BB*BPB = 512 blocks x 288 threads (9 warps).
// Warps 0-7 (producers): stream x, compute emissions for 8 rows each (R3 config,
//   proven DRAM 62%), write triples to smem double buffer. Never touch DRAM output.
// Warp 8 (consumer): while producers stream round k+1, scans round k's 64 steps
//   (in-lane pair combine + 5-level shuffle tree) and chains into a running block
//   product. Tail is overlapped with streaming by construction.
// Last block per batch (monotonic counter) reduces the 32 block partials; 16th
// batch-finalizer writes out[0]. Counters monotonic -> graph replays safe.
__global__ void __launch_bounds__(288) fused_kernel(const float* __restrict__ x,
                                                    const float* __restrict__ W,
                                                    const float* __restrict__ bias,
                                                    const int*   __restrict__ y,
                                                    const int*   __restrict__ mask,
                                                    const float* __restrict__ trans,
                                                    const float* __restrict__ start_t,
                                                    const float* __restrict__ end_t,
                                                    float* __restrict__ out) {
    __shared__ float buf[2][RR][3];        // emission triples, double-buffered
    __shared__ float tM[BPB * 9];
    __shared__ float tN[BPB];
    __shared__ int   tK[BPB];
    __shared__ int   s_flag;

    int b    = blockIdx.x >> 5;            // batch
    int blk  = blockIdx.x & (BPB - 1);     // block within batch
    int tid  = threadIdx.x;
    int wid  = tid >> 5;
    int lane = tid & 31;
    int bS   = b * SS;
    int rowbase = bS + blk * RPB;          // first flat row owned by this block

    float b0 = __ldg(bias + 0), b1 = __ldg(bias + 1), b2 = __ldg(bias + 2);
    float tr[9];
#pragma unroll
    for (int i = 0; i < 9; i++) tr[i] = __ldg(trans + i);

    // consumer running product (meaningful only in warp 8 lane 0); identity init
    float PP[9];
#pragma unroll
    for (int i = 0; i < 9; i++) PP[i] = NEGV;
    PP[0] = 0.f; PP[4] = 0.f; PP[8] = 0.f;
    float NS = 0.f; int MS = 0;

    for (int round = 0; round <= NPROD; round++) {
        // ---- producers: fill buf[round&1] with rows [round*64, +64) ----
        if (wid < 8 && round < NPROD) {
            int pb   = round & 1;
            int row0 = rowbase + round * RR + wid * 8;
            const float4* x4 = reinterpret_cast<const float4*>(x);
            const float4* w4 = reinterpret_cast<const float4*>(W);

            float a0[8], a1[8], a2[8];
#pragma unroll
            for (int r = 0; r < 8; r++) { a0[r] = 0.f; a1[r] = 0.f; a2[r] = 0.f; }
#pragma unroll
            for (int j = 0; j < 6; j++) {
                int idx = lane + 32 * j;              // 0..191
                float4 w0 = __ldg(w4 + idx);
                float4 w1 = __ldg(w4 + 192 + idx);
                float4 w2 = __ldg(w4 + 384 + idx);
#pragma unroll
                for (int r = 0; r < 8; r++) {
                    float4 xv = __ldg(x4 + (size_t)(row0 + r) * (HH / 4) + idx);
                    a0[r] = fmaf(xv.x, w0.x, fmaf(xv.y, w0.y, fmaf(xv.z, w0.z, fmaf(xv.w, w0.w, a0[r]))));
                    a1[r] = fmaf(xv.x, w1.x, fmaf(xv.y, w1.y, fmaf(xv.z, w1.z, fmaf(xv.w, w1.w, a1[r]))));
                    a2[r] = fmaf(xv.x, w2.x, fmaf(xv.y, w2.y, fmaf(xv.z, w2.z, fmaf(xv.w, w2.w, a2[r]))));
                }
            }
#pragma unroll
            for (int off = 16; off; off >>= 1) {
#pragma unroll
                for (int r = 0; r < 8; r++) {
                    a0[r] += __shfl_xor_sync(0xFFFFFFFFu, a0[r], off);
                    a1[r] += __shfl_xor_sync(0xFFFFFFFFu, a1[r], off);
                    a2[r] += __shfl_xor_sync(0xFFFFFFFFu, a2[r], off);
                }
            }
#pragma unroll
            for (int r = 0; r < 8; r++) {
                if (lane == r) {                       // compile-time r
                    int lr = wid * 8 + r;
                    buf[pb][lr][0] = a0[r] + b0;
                    buf[pb][lr][1] = a1[r] + b1;
                    buf[pb][lr][2] = a2[r] + b2;
                }
            }
        }

        // ---- consumer: scan previous round's buffer (overlaps streaming) ----
        if (wid == 8 && round >= 1) {
            int pb    = (round - 1) & 1;
            int sbase = blk * RPB + (round - 1) * RR;  // sequence position of buf row 0

            if (lane == 0 && blk == 0 && round == 1) { // batch row 0 emissions
                g_em0[b * 3 + 0] = buf[pb][0][0];
                g_em0[b * 3 + 1] = buf[pb][0][1];
                g_em0[b * 3 + 2] = buf[pb][0][2];
            }

            int lrA = 2 * lane, lrB = lrA + 1;
            int sA  = sbase + lrA;
            int tA  = bS + sA;

            float P[9];
            float nsum = 0.f;
            int   msum = 0;

            // step A
            {
                int mk = mask[tA];
                if (sA > 0 && mk) {
                    float e0 = buf[pb][lrA][0], e1 = buf[pb][lrA][1], e2 = buf[pb][lrA][2];
#pragma unroll
                    for (int i = 0; i < 3; i++) {
                        P[i * 3 + 0] = tr[i * 3 + 0] + e0;
                        P[i * 3 + 1] = tr[i * 3 + 1] + e1;
                        P[i * 3 + 2] = tr[i * 3 + 2] + e2;
                    }
                    int yt = y[tA], yp = y[tA - 1];
                    float ey = (yt == 0) ? e0 : ((yt == 1) ? e1 : e2);
                    nsum = tr[yp * 3 + yt] + ey;
                    msum = 1;
                } else {
#pragma unroll
                    for (int i = 0; i < 9; i++) P[i] = NEGV;
                    P[0] = 0.f; P[4] = 0.f; P[8] = 0.f;
                }
            }
            // step B (sB = sA+1 > 0 always): fold into P
            {
                int tB = tA + 1;
                int mk = mask[tB];
                if (mk) {
                    float e0 = buf[pb][lrB][0], e1 = buf[pb][lrB][1], e2 = buf[pb][lrB][2];
                    float C[9];
#pragma unroll
                    for (int i = 0; i < 3; i++) {
                        C[i * 3 + 0] = lse3(P[i * 3 + 0] + tr[0], P[i * 3 + 1] + tr[3], P[i * 3 + 2] + tr[6]) + e0;
                        C[i * 3 + 1] = lse3(P[i * 3 + 0] + tr[1], P[i * 3 + 1] + tr[4], P[i * 3 + 2] + tr[7]) + e1;
                        C[i * 3 + 2] = lse3(P[i * 3 + 0] + tr[2], P[i * 3 + 1] + tr[5], P[i * 3 + 2] + tr[8]) + e2;
                    }
#pragma unroll
                    for (int i = 0; i < 9; i++) P[i] = C[i];
                    int yt = y[tB], yp = y[tB - 1];
                    float ey = (yt == 0) ? e0 : ((yt == 1) ? e1 : e2);
                    nsum += tr[yp * 3 + yt] + ey;
                    msum += 1;
                }
            }

            // order-preserving suffix tree: lane 0 ends with the 64-step product
#pragma unroll
            for (int st = 1; st < 32; st <<= 1) {
                float Q[9];
#pragma unroll
                for (int i = 0; i < 9; i++) Q[i] = __shfl_down_sync(0xFFFFFFFFu, P[i], st);
                float nq = __shfl_down_sync(0xFFFFFFFFu, nsum, st);
                int   mq = __shfl_down_sync(0xFFFFFFFFu, msum, st);
                float C[9];
#pragma unroll
                for (int i = 0; i < 3; i++) {
#pragma unroll
                    for (int j = 0; j < 3; j++) {
                        C[i * 3 + j] = lse3(P[i * 3 + 0] + Q[0 * 3 + j],
                                            P[i * 3 + 1] + Q[1 * 3 + j],
                                            P[i * 3 + 2] + Q[2 * 3 + j]);
                    }
                }
#pragma unroll
                for (int i = 0; i < 9; i++) P[i] = C[i];
                nsum += nq;
                msum += mq;
            }

            if (lane == 0) {    // chain round product into running block product
                float C[9];
#pragma unroll
                for (int i = 0; i < 3; i++) {
#pragma unroll
                    for (int j = 0; j < 3; j++) {
                        C[i * 3 + j] = lse3(PP[i * 3 + 0] + P[0 * 3 + j],
                                            PP[i * 3 + 1] + P[1 * 3 + j],
                                            PP[i * 3 + 2] + P[2 * 3 + j]);
                    }
                }
#pragma unroll
                for (int i = 0; i < 9; i++) PP[i] = C[i];
                NS += nsum;
                MS += msum;
            }
        }
        __syncthreads();
    }

    // ---- publish block partial + arrival bump ----
    if (wid == 8 && lane == 0) {
        int pi = b * BPB + blk;
#pragma unroll
        for (int i = 0; i < 9; i++) g_part[pi * 9 + i] = PP[i];
        g_nump[pi] = NS;
        g_mskp[pi] = MS;
        __threadfence();
        unsigned int old = atomicAdd(&g_cnt[b], 1u);
        s_flag = ((old & (BPB - 1u)) == BPB - 1u) ? 1 : 0;   // mod 32 (graph replays)
    }
    __syncthreads();
    if (!s_flag) return;

    // ---- last block of batch b: reduce 32 block partials + finalize ----
    if (tid < BPB * 9) tM[tid] = __ldcg(&g_part[b * BPB * 9 + tid]);   // 288 = exactly
    if (tid < BPB) {
        tN[tid] = __ldcg(&g_nump[b * BPB + tid]);
        tK[tid] = __ldcg(&g_mskp[b * BPB + tid]);
    }
    __syncthreads();

    for (int st = 1; st < BPB; st <<= 1) {
        int pairs = BPB / (2 * st);
        int jobs  = pairs * 9;                 // max 144 <= 288 threads
        float cv = 0.f; int off = 0;
        bool doj = tid < jobs;
        if (doj) {
            int p = tid / 9, e = tid - p * 9;
            int i = e / 3, c = e - i * 3;
            int m = p * 2 * st;
            const float* A  = &tM[m * 9];
            const float* Bm = &tM[(m + st) * 9];
            cv  = lse3(A[i * 3 + 0] + Bm[0 + c],
                       A[i * 3 + 1] + Bm[3 + c],
                       A[i * 3 + 2] + Bm[6 + c]);
            off = m * 9 + e;
        }
        bool dos = tid < pairs;
        float nv = 0.f; int kv = 0;
        if (dos) { int m = tid * 2 * st; nv = tN[m] + tN[m + st]; kv = tK[m] + tK[m + st]; }
        __syncthreads();
        if (doj) tM[off] = cv;
        if (dos) { int m = tid * 2 * st; tN[m] = nv; tK[m] = kv; }
        __syncthreads();
    }

    if (tid == 0) {
        float e0 = __ldcg(&g_em0[b * 3 + 0]);
        float e1 = __ldcg(&g_em0[b * 3 + 1]);
        float e2 = __ldcg(&g_em0[b * 3 + 2]);
        float p0 = start_t[0] + e0;
        float p1 = start_t[1] + e1;
        float p2 = start_t[2] + e2;

        float af0 = lse3(p0 + tM[0], p1 + tM[3], p2 + tM[6]);
        float af1 = lse3(p0 + tM[1], p1 + tM[4], p2 + tM[7]);
        float af2 = lse3(p0 + tM[2], p1 + tM[5], p2 + tM[8]);
        float denom = lse3(af0 + end_t[0], af1 + end_t[1], af2 + end_t[2]);

        int y0 = y[bS];
        float em0y = (y0 == 0) ? e0 : ((y0 == 1) ? e1 : e2);
        float num  = start_t[y0] + em0y + tN[0];
        int   slen = mask[bS] + tK[0];
        num += end_t[y[bS + slen - 1]];

        g_llh[b] = num - denom;
        __threadfence();
        unsigned int ob = atomicAdd(&g_bcnt, 1u);
        if ((ob & (BB - 1u)) == BB - 1u) {                   // 16th finalizer
            float s = 0.f;
#pragma unroll
            for (int i = 0; i < BB; i++) s += __ldcg(&g_llh[i]);
            out[0] = -s / (float)BB;
        }
    }
}

// ---------------- launch ----------------------------------------------------------
extern "C" void kernel_launch(void* const* d_in, const int* in_sizes, int n_in,
                              void* d_out, int out_size) {
    const float* x     = (const float*)d_in[0];
    const int*   y     = (const int*)  d_in[1];
    const int*   mask  = (const int*)  d_in[2];
    const float* W     = (const float*)d_in[3];
    const float* bias  = (const float*)d_in[4];
    const float* st    = (const float*)d_in[5];
    const float* en    = (const float*)d_in[6];
    const float* trans = (const float*)d_in[7];
    float* out = (float*)d_out;

    fused_kernel<<<BB * BPB, 288>>>(x, W, bias, y, mask, trans, st, en, out);
}